// round 16
// baseline (speedup 1.0000x reference)
#include <cuda_runtime.h>
#include <cuda_bf16.h>

#define NB 16
#define NP 65536
#define NT 48
#define THRESH 0.35f
#define MBLKX 74           // match blocks per batch (ragged chunks)
#define CHUNK 886          // priors per match block (74*886 = 65564 >= NP)
#define LBLK 32            // loss blocks per batch   (NP / (256*8))
#define CBLK 32            // sumhist blocks per batch
#define FULLM 0xffffffffu

// ---------------- scratch (no allocation allowed) ----------------
__device__ unsigned long long g_bestprior[NB * NT];
__device__ unsigned char g_flag[NB * NP];       // (bt<<1)|pos, override-corrected
__device__ __align__(16) float g_ce[NB * NP];   // loss_rank (pos -> 0), all >= 0
__device__ unsigned g_hist0[NB * 2048];
__device__ unsigned g_h1cnt[NB * 2048];
__device__ float    g_h1sum[NB * 2048];
__device__ int g_b0[NB];
__device__ long long g_kkrem[NB];
__device__ long long g_k7[NB];
__device__ double g_sumgt[NB];
__device__ double g_tk[NB];
__device__ int g_done[NB];
__device__ int g_seldone;
__device__ double g_loss_l;
__device__ double g_loss_lm;
__device__ double g_cepos[NB];
__device__ int    g_numpos[NB];
__device__ int    g_nposland;

// ---------------- shared math ----------------
__device__ __forceinline__ float sl1(float d) {
    d = fabsf(d);
    return d < 1.f ? 0.5f * d * d : d - 0.5f;
}

struct PF { float x1, y1, x2, y2, area; };

__device__ __forceinline__ PF pointform(float4 pr) {
    PF r;
    r.x1 = __fmaf_rn(-0.5f, pr.z, pr.x);
    r.y1 = __fmaf_rn(-0.5f, pr.w, pr.y);
    r.x2 = __fmaf_rn( 0.5f, pr.z, pr.x);
    r.y2 = __fmaf_rn( 0.5f, pr.w, pr.y);
    r.area = __fmul_rn(__fsub_rn(r.x2, r.x1), __fsub_rn(r.y2, r.y1));
    return r;
}

// Intersection extents <= 0.3 < 1.0 here, so __saturatef == fmaxf(.,0)
// EXACTLY; SAT folds into the FADD as a destination modifier.
__device__ __forceinline__ float iou_pf(const PF& p, float4 b, float ba) {
    float w = __saturatef(__fsub_rn(fminf(p.x2, b.z), fmaxf(p.x1, b.x)));
    float h = __saturatef(__fsub_rn(fminf(p.y2, b.w), fmaxf(p.y1, b.y)));
    float inter = __fmul_rn(w, h);
    float den = __fsub_rn(__fadd_rn(p.area, ba), inter);
    return __fdividef(inter, den);          // inter==0 -> 0 (den>0 always)
}

__device__ __forceinline__ float calc_ll(const float* tg, float4 pr, float4 ld) {
    float inz = __fdividef(1.f, 0.1f * pr.z);
    float inw = __fdividef(1.f, 0.1f * pr.w);
    float t0 = ((tg[0] + tg[2]) * 0.5f - pr.x) * inz;
    float t1 = ((tg[1] + tg[3]) * 0.5f - pr.y) * inw;
    float t2 = __logf(__fdividef(tg[2] - tg[0], pr.z)) * 5.0f;
    float t3 = __logf(__fdividef(tg[3] - tg[1], pr.w)) * 5.0f;
    return sl1(ld.x - t0) + sl1(ld.y - t1) + sl1(ld.z - t2) + sl1(ld.w - t3);
}

__device__ __forceinline__ float calc_lm(const float* tg, float4 pr, const float2* lp) {
    float inz = __fdividef(1.f, 0.1f * pr.z);
    float inw = __fdividef(1.f, 0.1f * pr.w);
    float s = 0.f;
#pragma unroll
    for (int i = 0; i < 5; i++) {
        float2 d = lp[i];
        s += sl1(d.x - (tg[4 + 2 * i] - pr.x) * inz);
        s += sl1(d.y - (tg[5 + 2 * i] - pr.y) * inw);
    }
    return s;
}

__device__ __forceinline__ float calc_ce(float2 c, int cls) {
    float m = fmaxf(c.x, c.y);
    float ce = m + __logf(1.f + __expf(-fabsf(c.x - c.y))) - (cls ? c.y : c.x);
    return fmaxf(ce, 0.f);
}

// warp-aggregated shared-hist add (warp fully converged at call site)
__device__ __forceinline__ void hist_add(unsigned* s_h, unsigned bin) {
    unsigned m = __match_any_sync(FULLM, bin);
    unsigned lane = threadIdx.x & 31;
    if ((m & ((1u << lane) - 1)) == 0)
        atomicAdd(&s_h[bin], __popc(m));
}

// pick kth-from-top bin out of a GLOBAL histogram (block-cooperative)
__device__ __forceinline__ void pick_scan(const unsigned* gh, int nbins, long long kk,
                                          unsigned* s_hist, unsigned* s_chunk,
                                          int* s_bin, long long* s_kk) {
    for (int j = threadIdx.x; j < nbins; j += blockDim.x) s_hist[j] = gh[j];
    __syncthreads();
    int nchunk = nbins >> 3;
    for (int j = threadIdx.x; j < nchunk; j += blockDim.x) {
        unsigned s = 0;
#pragma unroll
        for (int q = 0; q < 8; q++) s += s_hist[j * 8 + q];
        s_chunk[j] = s;
    }
    __syncthreads();
    if (threadIdx.x == 0) {
        long long cum = 0;
        int c = nchunk - 1;
        for (; c > 0; c--) {
            long long cnt = (long long)s_chunk[c];
            if (cum + cnt >= kk) break;
            cum += cnt;
        }
        int b = c * 8;
        for (int j = c * 8 + 7; j >= c * 8; j--) {
            long long cnt = (long long)s_hist[j];
            if (cum + cnt >= kk) { b = j; break; }
            cum += cnt;
        }
        *s_bin = b;
        *s_kk = kk - cum;
    }
    __syncthreads();
}

// ---------------- init shards (3 launches so match is launch #4) ------
__global__ void init_a() {
    int i = threadIdx.x;
    if (i == 0) { g_loss_l = 0.0; g_loss_lm = 0.0; g_nposland = 0; g_seldone = 0; }
    if (i < NB) {
        g_cepos[i] = 0.0; g_numpos[i] = 0; g_done[i] = 0;
        g_sumgt[i] = 0.0; g_tk[i] = 0.0; g_k7[i] = 0;
        g_b0[i] = 0; g_kkrem[i] = 0;
    }
    for (int j = i; j < NB * NT; j += 256) g_bestprior[j] = 0xFFFFFFFFull;
}
__global__ void init_b() {
    int i = blockIdx.x * blockDim.x + threadIdx.x;
    for (int j = i; j < NB * 2048; j += gridDim.x * blockDim.x) g_hist0[j] = 0u;
}
__global__ void init_c() {
    int i = blockIdx.x * blockDim.x + threadIdx.x;
    for (int j = i; j < NB * 2048; j += gridDim.x * blockDim.x) {
        g_h1cnt[j] = 0u; g_h1sum[j] = 0.f;
    }
}

// ---------------- kernel: pure match, wave-balanced ----------------
// grid (74, NB): 1184 blocks; 44KB smem pad pins residency to 4 blocks/SM
// (148*4 = 592) -> exactly 2.0 uniform waves. 4 priors/thread, ragged
// 886-prior chunks with validity masks.
__global__ void __launch_bounds__(256, 4) match_kernel(
    const float4* __restrict__ priors,
    const float*  __restrict__ targets)
{
    __shared__ float4 s_box[NT];
    __shared__ float  s_area[NT];
    __shared__ unsigned s_wm[NT * 8];       // per-(truth,warp) max iou bits
    __shared__ int s_last;
    __shared__ int s_p[NT];
    __shared__ char s_pad[44032];           // residency limiter: 4 blocks/SM

    const int n = blockIdx.y;
    const int tid = threadIdx.x;
    const int wid = tid >> 5, lane = tid & 31;

    if (tid == 0) ((volatile char*)s_pad)[0] = 0;   // keep the pad live

    if (tid < NT) {
        const float* tg = targets + (n * NT + tid) * 15;
        float4 b = make_float4(tg[0], tg[1], tg[2], tg[3]);
        s_box[tid] = b;
        s_area[tid] = __fmul_rn(__fsub_rn(b.z, b.x), __fsub_rn(b.w, b.y));
    }
    __syncthreads();

    const int base = blockIdx.x * CHUNK;
    const int pend = min(base + CHUNK, NP);
    int p[4];
    bool val[4];
    PF pf[4];
    float bo[4];
    int bt[4];
#pragma unroll
    for (int i = 0; i < 4; i++) {
        p[i] = base + tid + i * 256;
        val[i] = p[i] < pend;
        pf[i] = pointform(priors[min(p[i], NP - 1)]);   // clamped-safe load
        bo[i] = -1.f; bt[i] = 0;
    }

#pragma unroll 2
    for (int t = 0; t < NT; t++) {
        float4 b = s_box[t];
        float at = s_area[t];
        unsigned u[4];
#pragma unroll
        for (int i = 0; i < 4; i++) {
            float iou = iou_pf(pf[i], b, at);
            if (iou > bo[i]) { bo[i] = iou; bt[i] = t; }
            u[i] = val[i] ? __float_as_uint(iou) : 0u;  // iou>=0: bits monotone
        }
        unsigned m4 = max(max(u[0], u[1]), max(u[2], u[3]));
        unsigned wm = __reduce_max_sync(FULLM, m4);
        if (lane == 0) s_wm[t * 8 + wid] = wm;
    }
    __syncthreads();

    // ---- column-max cleanup: winning warp(s) recompute & push to global ----
    for (int t = 0; t < NT; t++) {
        unsigned v = (lane < 8) ? s_wm[t * 8 + lane] : 0u;
        unsigned bm = __reduce_max_sync(FULLM, v);
        unsigned mywm = s_wm[t * 8 + wid];
        if (bm != 0u && mywm == bm) {           // warp-uniform branch
            float4 b = s_box[t];
            float at = s_area[t];
            unsigned minp = FULLM;
#pragma unroll
            for (int i = 0; i < 4; i++) {
                float iou = iou_pf(pf[i], b, at);   // bit-identical recompute
                if (val[i] && __float_as_uint(iou) == bm)
                    minp = min(minp, (unsigned)p[i]);
            }
            minp = __reduce_min_sync(FULLM, minp);
            if (lane == 0)
                atomicMax(&g_bestprior[n * NT + t],
                          ((unsigned long long)bm << 32) | (FULLM - minp));
        }
    }

    // ---- write per-prior flags (pre-override) ----
#pragma unroll
    for (int i = 0; i < 4; i++) {
        if (val[i]) {
            unsigned char f = (bo[i] >= THRESH)
                            ? (unsigned char)((bt[i] << 1) | 1)
                            : (unsigned char)0;
            g_flag[n * NP + p[i]] = f;
        }
    }

    // ---- last-block-per-batch: apply override to flags (last-wins) ----
    __threadfence();
    if (tid == 0) {
        int dcount = atomicAdd(&g_done[n], 1);
        s_last = (dcount == MBLKX - 1);
        __threadfence();
    }
    __syncthreads();
    if (s_last) {
        if (tid < NT) {
            unsigned long long v = g_bestprior[n * NT + tid];
            s_p[tid] = (int)(FULLM - (unsigned)(v & 0xFFFFFFFFull));
        }
        __syncthreads();
        if (tid < NT) {
            int pp = s_p[tid];
            bool surv = true;                  // last-wins per prior
            for (int t2 = tid + 1; t2 < NT; t2++)
                if (s_p[t2] == pp) { surv = false; break; }
            if (surv)
                g_flag[n * NP + pp] = (unsigned char)((tid << 1) | 1);
        }
    }
}

// ---------------- kernel: loss from corrected flags ----------------
// grid (LBLK, NB), 256 threads, 8 priors/thread.
__global__ void __launch_bounds__(256) loss_kernel(
    const float4* __restrict__ loc,
    const float2* __restrict__ conf,
    const float2* __restrict__ landm,
    const float4* __restrict__ priors,
    const float*  __restrict__ targets)
{
    __shared__ float s_tg[NT * 15];
    __shared__ unsigned s_h[2048];
    __shared__ float r_a[8], r_b[8], r_c[8];
    __shared__ int r_d[8], r_e[8];

    const int n = blockIdx.y;
    const int tid = threadIdx.x;
    const int wid = tid >> 5, lane = tid & 31;

    for (int j = tid; j < NT * 15; j += 256)
        s_tg[j] = targets[n * NT * 15 + j];
    for (int j = tid; j < 2048; j += 256)
        s_h[j] = 0u;
    __syncthreads();

    float ll = 0.f, lm = 0.f, cep = 0.f;
    int dpos = 0, dland = 0;
#pragma unroll
    for (int j = 0; j < 8; j++) {
        const int p = blockIdx.x * 2048 + j * 256 + tid;
        const int idx = n * NP + p;
        const unsigned f = g_flag[idx];
        const int bt = (int)(f >> 1);
        const float* tg = &s_tg[bt * 15];
        const int conft = (f & 1u) ? (int)tg[14] : 0;
        const bool pos = (conft != 0);
        const bool posland = (conft > 0);

        float2 c = conf[idx];
        float ce = calc_ce(c, pos ? 1 : 0);
        float cev = pos ? 0.f : ce;
        g_ce[idx] = cev;
        hist_add(s_h, __float_as_uint(cev) >> 21);

        if (pos) {
            cep += ce;
            dpos++;
            float4 pr = priors[p];
            ll += calc_ll(tg, pr, loc[idx]);
            if (posland) {
                dland++;
                lm += calc_lm(tg, pr, &landm[(size_t)idx * 5]);
            }
        }
    }

    float a = ll, b2 = lm, cc = cep;
    int d = dpos, e = dland;
#pragma unroll
    for (int o = 16; o; o >>= 1) {
        a  += __shfl_down_sync(FULLM, a, o);
        b2 += __shfl_down_sync(FULLM, b2, o);
        cc += __shfl_down_sync(FULLM, cc, o);
        d  += __shfl_down_sync(FULLM, d, o);
        e  += __shfl_down_sync(FULLM, e, o);
    }
    if (lane == 0) { r_a[wid] = a; r_b[wid] = b2; r_c[wid] = cc; r_d[wid] = d; r_e[wid] = e; }
    __syncthreads();
    if (tid == 0) {
        float A2 = 0, B3 = 0, C = 0; int D = 0, E = 0;
#pragma unroll
        for (int w = 0; w < 8; w++) { A2 += r_a[w]; B3 += r_b[w]; C += r_c[w]; D += r_d[w]; E += r_e[w]; }
        if (A2 != 0.f) atomicAdd(&g_loss_l, (double)A2);
        if (B3 != 0.f) atomicAdd(&g_loss_lm, (double)B3);
        if (C != 0.f) atomicAdd(&g_cepos[n], (double)C);
        if (D) atomicAdd(&g_numpos[n], D);
        if (E) atomicAdd(&g_nposland, E);
    }
    for (int j = tid; j < 2048; j += 256) {
        unsigned v = s_h[j];
        if (v) atomicAdd(&g_hist0[n * 2048 + j], v);
    }
}

// ---------------- sumhist: inline pick0 + stream g_ce once ----------------
__global__ void __launch_bounds__(256) sumhist_kernel() {
    __shared__ unsigned s_cnt[2048];
    __shared__ float s_sum[2048];
    __shared__ unsigned s_chunk[256];
    __shared__ int s_bin;
    __shared__ long long s_kk;

    const int n = blockIdx.y;
    const int tid = threadIdx.x;
    long long k = 7LL * (long long)g_numpos[n];
    if (k > NP - 1) k = NP - 1;
    if (blockIdx.x == 0 && tid == 0) g_k7[n] = k;
    if (k <= 0) return;

    pick_scan(&g_hist0[n * 2048], 2048, k, s_cnt, s_chunk, &s_bin, &s_kk);
    const unsigned b0 = (unsigned)s_bin;
    if (blockIdx.x == 0 && tid == 0) { g_b0[n] = s_bin; g_kkrem[n] = s_kk; }
    __syncthreads();

    for (int j = tid; j < 2048; j += 256) { s_cnt[j] = 0u; s_sum[j] = 0.f; }
    __syncthreads();

    const uint4* k4 = reinterpret_cast<const uint4*>(&g_ce[n * NP]);
    const int base = blockIdx.x * (NP / 4 / CBLK);
    double s = 0.0;
    for (int i = tid; i < NP / 4 / CBLK; i += 256) {
        uint4 v = k4[base + i];
#pragma unroll
        for (int j = 0; j < 4; j++) {
            unsigned key = (j == 0) ? v.x : (j == 1) ? v.y : (j == 2) ? v.z : v.w;
            unsigned pref = key >> 21;
            if (pref > b0) {
                s += (double)__uint_as_float(key);
            } else if (pref == b0) {
                unsigned mid = (key >> 10) & 0x7FFu;
                atomicAdd(&s_cnt[mid], 1u);
                atomicAdd(&s_sum[mid], __uint_as_float(key));
            }
        }
    }
#pragma unroll
    for (int o = 16; o; o >>= 1) s += __shfl_down_sync(FULLM, s, o);
    __shared__ double r_s[8];
    int wid = tid >> 5, lane = tid & 31;
    if (lane == 0) r_s[wid] = s;
    __syncthreads();
    if (tid == 0) {
        double S = 0;
#pragma unroll
        for (int w = 0; w < 8; w++) S += r_s[w];
        if (S != 0.0) atomicAdd(&g_sumgt[n], S);
    }
    for (int j = tid; j < 2048; j += 256) {
        unsigned cv = s_cnt[j];
        if (cv) atomicAdd(&g_h1cnt[n * 2048 + j], cv);
        float fv = s_sum[j];
        if (fv != 0.f) atomicAdd(&g_h1sum[n * 2048 + j], fv);
    }
}

// ---------------- final: pick b1, assemble topk, combine ----------------
__global__ void final_kernel(float* __restrict__ out) {
    __shared__ unsigned s_hist[2048];
    __shared__ unsigned s_chunk[256];
    __shared__ int s_bin;
    __shared__ long long s_kk;
    __shared__ double r_s[8];
    __shared__ int s_last;

    const int n = blockIdx.x;
    const int tid = threadIdx.x;
    const long long k = g_k7[n];

    if (k > 0) {
        pick_scan(&g_h1cnt[n * 2048], 2048, g_kkrem[n], s_hist, s_chunk, &s_bin, &s_kk);
        const int b1 = s_bin;
        const long long rem = s_kk;

        double sa = 0.0;
        for (int j = tid; j < 2048; j += 256)
            if (j > b1) sa += (double)g_h1sum[n * 2048 + j];
#pragma unroll
        for (int o = 16; o; o >>= 1) sa += __shfl_down_sync(FULLM, sa, o);
        int wid = tid >> 5, lane = tid & 31;
        if (lane == 0) r_s[wid] = sa;
        __syncthreads();
        if (tid == 0) {
            double SA = 0;
#pragma unroll
            for (int w = 0; w < 8; w++) SA += r_s[w];
            float rep = __uint_as_float(((unsigned)g_b0[n] << 21) |
                                        ((unsigned)b1 << 10) | 0x200u);
            g_tk[n] = g_sumgt[n] + SA + (double)rem * (double)rep;
        }
    } else if (tid == 0) {
        g_tk[n] = 0.0;
    }

    if (tid == 0) {
        __threadfence();
        int dcount = atomicAdd(&g_seldone, 1);
        s_last = (dcount == NB - 1);
        __threadfence();
    }
    __syncthreads();
    if (s_last && tid == 0) {
        double lc = 0.0;
        long long np = 0;
        for (int b = 0; b < NB; b++) {
            lc += g_cepos[b] + g_tk[b];
            np += g_numpos[b];
        }
        double Nn = np < 1 ? 1.0 : (double)np;
        int npl = g_nposland;
        double N1 = npl < 1 ? 1.0 : (double)npl;
        out[0] = (float)(g_loss_l / Nn);
        out[1] = (float)(lc / Nn);
        out[2] = (float)(g_loss_lm / N1);
    }
}

extern "C" void kernel_launch(void* const* d_in, const int* in_sizes, int n_in,
                              void* d_out, int out_size) {
    const float4* loc     = (const float4*)d_in[0];   // (16,65536,4) f32
    const float2* conf    = (const float2*)d_in[1];   // (16,65536,2) f32
    const float2* landm   = (const float2*)d_in[2];   // (16,65536,10) f32
    const float4* priors  = (const float4*)d_in[3];   // (65536,4) f32
    const float*  targets = (const float*)d_in[4];    // (16,48,15) f32
    float* out = (float*)d_out;

    init_a<<<1, 256>>>();
    init_b<<<16, 256>>>();
    init_c<<<16, 256>>>();                            // match = launch #4
    match_kernel<<<dim3(MBLKX, NB), 256>>>(priors, targets);
    loss_kernel<<<dim3(LBLK, NB), 256>>>(loc, conf, landm, priors, targets);
    sumhist_kernel<<<dim3(CBLK, NB), 256>>>();
    final_kernel<<<NB, 256>>>(out);
}

// round 17
// speedup vs baseline: 1.0960x; 1.0960x over previous
#include <cuda_runtime.h>
#include <cuda_bf16.h>

#define NB 16
#define NP 65536
#define NT 48
#define THRESH 0.35f
#define MBLK 64            // match blocks per batch  (NP / (256*4))
#define LBLK 32            // loss blocks per batch   (NP / (256*8))
#define CBLK 32            // sumhist blocks per batch
#define FULLM 0xffffffffu

// ---------------- scratch (no allocation allowed) ----------------
__device__ unsigned long long g_bestprior[NB * NT];
__device__ unsigned char g_flag[NB * NP];       // (bt<<1)|pos, override-corrected
__device__ __align__(16) float g_ce[NB * NP];   // loss_rank (pos -> 0), all >= 0
__device__ unsigned g_hist0[NB * 2048];
__device__ unsigned g_h1cnt[NB * 2048];
__device__ float    g_h1sum[NB * 2048];
__device__ int g_b0[NB];
__device__ long long g_kkrem[NB];
__device__ long long g_k7[NB];
__device__ double g_sumgt[NB];
__device__ double g_tk[NB];
__device__ int g_done[NB];
__device__ int g_ldone[NB];
__device__ int g_seldone;
__device__ double g_loss_l;
__device__ double g_loss_lm;
__device__ double g_cepos[NB];
__device__ int    g_numpos[NB];
__device__ int    g_nposland;

// ---------------- shared math ----------------
__device__ __forceinline__ float sl1(float d) {
    d = fabsf(d);
    return d < 1.f ? 0.5f * d * d : d - 0.5f;
}

struct PF { float x1, y1, x2, y2, area; };

__device__ __forceinline__ PF pointform(float4 pr) {
    PF r;
    r.x1 = __fmaf_rn(-0.5f, pr.z, pr.x);
    r.y1 = __fmaf_rn(-0.5f, pr.w, pr.y);
    r.x2 = __fmaf_rn( 0.5f, pr.z, pr.x);
    r.y2 = __fmaf_rn( 0.5f, pr.w, pr.y);
    r.area = __fmul_rn(__fsub_rn(r.x2, r.x1), __fsub_rn(r.y2, r.y1));
    return r;
}

// Intersection extents <= 0.3 < 1.0 here, so __saturatef == fmaxf(.,0)
// EXACTLY; SAT folds into the FADD as a destination modifier.
__device__ __forceinline__ float iou_pf(const PF& p, float4 b, float ba) {
    float w = __saturatef(__fsub_rn(fminf(p.x2, b.z), fmaxf(p.x1, b.x)));
    float h = __saturatef(__fsub_rn(fminf(p.y2, b.w), fmaxf(p.y1, b.y)));
    float inter = __fmul_rn(w, h);
    float den = __fsub_rn(__fadd_rn(p.area, ba), inter);
    return __fdividef(inter, den);          // inter==0 -> 0 (den>0 always)
}

__device__ __forceinline__ float calc_ll(const float* tg, float4 pr, float4 ld) {
    float inz = __fdividef(1.f, 0.1f * pr.z);
    float inw = __fdividef(1.f, 0.1f * pr.w);
    float t0 = ((tg[0] + tg[2]) * 0.5f - pr.x) * inz;
    float t1 = ((tg[1] + tg[3]) * 0.5f - pr.y) * inw;
    float t2 = __logf(__fdividef(tg[2] - tg[0], pr.z)) * 5.0f;
    float t3 = __logf(__fdividef(tg[3] - tg[1], pr.w)) * 5.0f;
    return sl1(ld.x - t0) + sl1(ld.y - t1) + sl1(ld.z - t2) + sl1(ld.w - t3);
}

__device__ __forceinline__ float calc_lm(const float* tg, float4 pr, const float2* lp) {
    float inz = __fdividef(1.f, 0.1f * pr.z);
    float inw = __fdividef(1.f, 0.1f * pr.w);
    float s = 0.f;
#pragma unroll
    for (int i = 0; i < 5; i++) {
        float2 d = lp[i];
        s += sl1(d.x - (tg[4 + 2 * i] - pr.x) * inz);
        s += sl1(d.y - (tg[5 + 2 * i] - pr.y) * inw);
    }
    return s;
}

__device__ __forceinline__ float calc_ce(float2 c, int cls) {
    float m = fmaxf(c.x, c.y);
    float ce = m + __logf(1.f + __expf(-fabsf(c.x - c.y))) - (cls ? c.y : c.x);
    return fmaxf(ce, 0.f);
}

// warp-aggregated shared-hist add (warp fully converged at call site)
__device__ __forceinline__ void hist_add(unsigned* s_h, unsigned bin) {
    unsigned m = __match_any_sync(FULLM, bin);
    unsigned lane = threadIdx.x & 31;
    if ((m & ((1u << lane) - 1)) == 0)
        atomicAdd(&s_h[bin], __popc(m));
}

// pick kth-from-top bin out of a GLOBAL histogram (block-cooperative)
__device__ __forceinline__ void pick_scan(const unsigned* gh, int nbins, long long kk,
                                          unsigned* s_hist, unsigned* s_chunk,
                                          int* s_bin, long long* s_kk) {
    for (int j = threadIdx.x; j < nbins; j += blockDim.x) s_hist[j] = gh[j];
    __syncthreads();
    int nchunk = nbins >> 3;
    for (int j = threadIdx.x; j < nchunk; j += blockDim.x) {
        unsigned s = 0;
#pragma unroll
        for (int q = 0; q < 8; q++) s += s_hist[j * 8 + q];
        s_chunk[j] = s;
    }
    __syncthreads();
    if (threadIdx.x == 0) {
        long long cum = 0;
        int c = nchunk - 1;
        for (; c > 0; c--) {
            long long cnt = (long long)s_chunk[c];
            if (cum + cnt >= kk) break;
            cum += cnt;
        }
        int b = c * 8;
        for (int j = c * 8 + 7; j >= c * 8; j--) {
            long long cnt = (long long)s_hist[j];
            if (cum + cnt >= kk) { b = j; break; }
            cum += cnt;
        }
        *s_bin = b;
        *s_kk = kk - cum;
    }
    __syncthreads();
}

// ---------------- kernel 0: single init ----------------
__global__ void init_kernel() {
    int i = blockIdx.x * blockDim.x + threadIdx.x;
    int nthr = gridDim.x * blockDim.x;
    if (i == 0) { g_loss_l = 0.0; g_loss_lm = 0.0; g_nposland = 0; g_seldone = 0; }
    if (i < NB) {
        g_cepos[i] = 0.0; g_numpos[i] = 0; g_done[i] = 0; g_ldone[i] = 0;
        g_sumgt[i] = 0.0; g_tk[i] = 0.0; g_k7[i] = 0;
        g_b0[i] = 0; g_kkrem[i] = 0;
    }
    for (int j = i; j < NB * NT; j += nthr) g_bestprior[j] = 0xFFFFFFFFull;
    for (int j = i; j < NB * 2048; j += nthr) {
        g_hist0[j] = 0u; g_h1cnt[j] = 0u; g_h1sum[j] = 0.f;
    }
}

// ---------------- kernel 1: pure match (4 priors/thread, R15 form) --------
// Writes per-prior flag (bt<<1)|pos; last block per batch applies the
// reference's best-prior override DIRECTLY to the flags (last-wins).
__global__ void __launch_bounds__(256, 5) match_kernel(
    const float4* __restrict__ priors,
    const float*  __restrict__ targets)
{
    __shared__ float4 s_box[NT];
    __shared__ float  s_area[NT];
    __shared__ unsigned s_wm[NT * 8];       // per-(truth,warp) max iou bits
    __shared__ int s_last;
    __shared__ int s_p[NT];

    const int n = blockIdx.y;
    const int tid = threadIdx.x;
    const int wid = tid >> 5, lane = tid & 31;

    if (tid < NT) {
        const float* tg = targets + (n * NT + tid) * 15;
        float4 b = make_float4(tg[0], tg[1], tg[2], tg[3]);
        s_box[tid] = b;
        s_area[tid] = __fmul_rn(__fsub_rn(b.z, b.x), __fsub_rn(b.w, b.y));
    }
    __syncthreads();

    const int pbase = blockIdx.x * 1024 + tid;
    PF pf[4];
    float bo[4];
    int bt[4];
#pragma unroll
    for (int i = 0; i < 4; i++) {
        pf[i] = pointform(priors[pbase + i * 256]);
        bo[i] = -1.f; bt[i] = 0;
    }

#pragma unroll 2
    for (int t = 0; t < NT; t++) {
        float4 b = s_box[t];
        float at = s_area[t];
        unsigned u[4];
#pragma unroll
        for (int i = 0; i < 4; i++) {
            float iou = iou_pf(pf[i], b, at);
            if (iou > bo[i]) { bo[i] = iou; bt[i] = t; }
            u[i] = __float_as_uint(iou);        // iou>=0: bits monotone
        }
        unsigned m4 = max(max(u[0], u[1]), max(u[2], u[3]));
        unsigned wm = __reduce_max_sync(FULLM, m4);
        if (lane == 0) s_wm[t * 8 + wid] = wm;
    }
    __syncthreads();

    // ---- column-max cleanup: winning warp(s) recompute & push to global ----
    for (int t = 0; t < NT; t++) {
        unsigned v = (lane < 8) ? s_wm[t * 8 + lane] : 0u;
        unsigned bm = __reduce_max_sync(FULLM, v);
        unsigned mywm = s_wm[t * 8 + wid];
        if (bm != 0u && mywm == bm) {           // warp-uniform branch
            float4 b = s_box[t];
            float at = s_area[t];
            unsigned minp = FULLM;
#pragma unroll
            for (int i = 0; i < 4; i++) {
                float iou = iou_pf(pf[i], b, at);   // bit-identical recompute
                if (__float_as_uint(iou) == bm)
                    minp = min(minp, (unsigned)(pbase + i * 256));
            }
            minp = __reduce_min_sync(FULLM, minp);
            if (lane == 0)
                atomicMax(&g_bestprior[n * NT + t],
                          ((unsigned long long)bm << 32) | (FULLM - minp));
        }
    }

    // ---- write per-prior flags (pre-override) ----
#pragma unroll
    for (int i = 0; i < 4; i++) {
        unsigned char f = (bo[i] >= THRESH)
                        ? (unsigned char)((bt[i] << 1) | 1)
                        : (unsigned char)0;
        g_flag[n * NP + pbase + i * 256] = f;
    }

    // ---- last-block-per-batch: apply override to flags (last-wins) ----
    __threadfence();
    if (tid == 0) {
        int dcount = atomicAdd(&g_done[n], 1);
        s_last = (dcount == MBLK - 1);
        __threadfence();
    }
    __syncthreads();
    if (s_last) {
        if (tid < NT) {
            unsigned long long v = g_bestprior[n * NT + tid];
            s_p[tid] = (int)(FULLM - (unsigned)(v & 0xFFFFFFFFull));
        }
        __syncthreads();
        if (tid < NT) {
            int pp = s_p[tid];
            bool surv = true;                  // last-wins per prior
            for (int t2 = tid + 1; t2 < NT; t2++)
                if (s_p[t2] == pp) { surv = false; break; }
            if (surv)
                g_flag[n * NP + pp] = (unsigned char)((tid << 1) | 1);
        }
    }
}

// ---------------- kernel 2: loss from corrected flags + last-block pick0 ---
// grid (LBLK, NB), 256 threads, 8 priors/thread.
__global__ void __launch_bounds__(256) loss_kernel(
    const float4* __restrict__ loc,
    const float2* __restrict__ conf,
    const float2* __restrict__ landm,
    const float4* __restrict__ priors,
    const float*  __restrict__ targets)
{
    __shared__ float s_tg[NT * 15];
    __shared__ unsigned s_h[2048];
    __shared__ unsigned s_chunk[256];
    __shared__ float r_a[8], r_b[8], r_c[8];
    __shared__ int r_d[8], r_e[8];
    __shared__ int s_last, s_bin;
    __shared__ long long s_kk;

    const int n = blockIdx.y;
    const int tid = threadIdx.x;
    const int wid = tid >> 5, lane = tid & 31;

    for (int j = tid; j < NT * 15; j += 256)
        s_tg[j] = targets[n * NT * 15 + j];
    for (int j = tid; j < 2048; j += 256)
        s_h[j] = 0u;
    __syncthreads();

    float ll = 0.f, lm = 0.f, cep = 0.f;
    int dpos = 0, dland = 0;
#pragma unroll
    for (int j = 0; j < 8; j++) {
        const int p = blockIdx.x * 2048 + j * 256 + tid;
        const int idx = n * NP + p;
        const unsigned f = g_flag[idx];
        const int bt = (int)(f >> 1);
        const float* tg = &s_tg[bt * 15];
        const int conft = (f & 1u) ? (int)tg[14] : 0;
        const bool pos = (conft != 0);
        const bool posland = (conft > 0);

        float2 c = conf[idx];
        float ce = calc_ce(c, pos ? 1 : 0);
        float cev = pos ? 0.f : ce;
        g_ce[idx] = cev;
        hist_add(s_h, __float_as_uint(cev) >> 21);

        if (pos) {
            cep += ce;
            dpos++;
            float4 pr = priors[p];
            ll += calc_ll(tg, pr, loc[idx]);
            if (posland) {
                dland++;
                lm += calc_lm(tg, pr, &landm[(size_t)idx * 5]);
            }
        }
    }

    float a = ll, b2 = lm, cc = cep;
    int d = dpos, e = dland;
#pragma unroll
    for (int o = 16; o; o >>= 1) {
        a  += __shfl_down_sync(FULLM, a, o);
        b2 += __shfl_down_sync(FULLM, b2, o);
        cc += __shfl_down_sync(FULLM, cc, o);
        d  += __shfl_down_sync(FULLM, d, o);
        e  += __shfl_down_sync(FULLM, e, o);
    }
    if (lane == 0) { r_a[wid] = a; r_b[wid] = b2; r_c[wid] = cc; r_d[wid] = d; r_e[wid] = e; }
    __syncthreads();
    if (tid == 0) {
        float A2 = 0, B3 = 0, C = 0; int D = 0, E = 0;
#pragma unroll
        for (int w = 0; w < 8; w++) { A2 += r_a[w]; B3 += r_b[w]; C += r_c[w]; D += r_d[w]; E += r_e[w]; }
        if (A2 != 0.f) atomicAdd(&g_loss_l, (double)A2);
        if (B3 != 0.f) atomicAdd(&g_loss_lm, (double)B3);
        if (C != 0.f) atomicAdd(&g_cepos[n], (double)C);
        if (D) atomicAdd(&g_numpos[n], D);
        if (E) atomicAdd(&g_nposland, E);
    }
    for (int j = tid; j < 2048; j += 256) {
        unsigned v = s_h[j];
        if (v) atomicAdd(&g_hist0[n * 2048 + j], v);
    }

    // ---- last-block-per-batch: pick0 (hist0 complete for this batch) ----
    __threadfence();
    if (tid == 0) {
        int dcount = atomicAdd(&g_ldone[n], 1);
        s_last = (dcount == LBLK - 1);
        __threadfence();
    }
    __syncthreads();
    if (s_last) {
        long long k = 7LL * (long long)g_numpos[n];   // complete (fenced)
        if (k > NP - 1) k = NP - 1;
        if (tid == 0) g_k7[n] = k;
        if (k > 0) {
            pick_scan(&g_hist0[n * 2048], 2048, k, s_h, s_chunk, &s_bin, &s_kk);
            if (tid == 0) { g_b0[n] = s_bin; g_kkrem[n] = s_kk; }
        }
    }
}

// ---------------- kernel 3: sumhist (b0 precomputed by loss) ----------------
__global__ void __launch_bounds__(256) sumhist_kernel() {
    __shared__ unsigned s_cnt[2048];
    __shared__ float s_sum[2048];

    const int n = blockIdx.y;
    const int tid = threadIdx.x;
    if (g_k7[n] <= 0) return;
    const unsigned b0 = (unsigned)g_b0[n];

    for (int j = tid; j < 2048; j += 256) { s_cnt[j] = 0u; s_sum[j] = 0.f; }
    __syncthreads();

    const uint4* k4 = reinterpret_cast<const uint4*>(&g_ce[n * NP]);
    const int base = blockIdx.x * (NP / 4 / CBLK);
    double s = 0.0;
    for (int i = tid; i < NP / 4 / CBLK; i += 256) {
        uint4 v = k4[base + i];
#pragma unroll
        for (int j = 0; j < 4; j++) {
            unsigned key = (j == 0) ? v.x : (j == 1) ? v.y : (j == 2) ? v.z : v.w;
            unsigned pref = key >> 21;
            if (pref > b0) {
                s += (double)__uint_as_float(key);
            } else if (pref == b0) {
                unsigned mid = (key >> 10) & 0x7FFu;
                atomicAdd(&s_cnt[mid], 1u);
                atomicAdd(&s_sum[mid], __uint_as_float(key));
            }
        }
    }
#pragma unroll
    for (int o = 16; o; o >>= 1) s += __shfl_down_sync(FULLM, s, o);
    __shared__ double r_s[8];
    int wid = tid >> 5, lane = tid & 31;
    if (lane == 0) r_s[wid] = s;
    __syncthreads();
    if (tid == 0) {
        double S = 0;
#pragma unroll
        for (int w = 0; w < 8; w++) S += r_s[w];
        if (S != 0.0) atomicAdd(&g_sumgt[n], S);
    }
    for (int j = tid; j < 2048; j += 256) {
        unsigned cv = s_cnt[j];
        if (cv) atomicAdd(&g_h1cnt[n * 2048 + j], cv);
        float fv = s_sum[j];
        if (fv != 0.f) atomicAdd(&g_h1sum[n * 2048 + j], fv);
    }
}

// ---------------- kernel 4: pick b1, assemble topk, combine ----------------
__global__ void final_kernel(float* __restrict__ out) {
    __shared__ unsigned s_hist[2048];
    __shared__ unsigned s_chunk[256];
    __shared__ int s_bin;
    __shared__ long long s_kk;
    __shared__ double r_s[8];
    __shared__ int s_last;

    const int n = blockIdx.x;
    const int tid = threadIdx.x;
    const long long k = g_k7[n];

    if (k > 0) {
        pick_scan(&g_h1cnt[n * 2048], 2048, g_kkrem[n], s_hist, s_chunk, &s_bin, &s_kk);
        const int b1 = s_bin;
        const long long rem = s_kk;

        double sa = 0.0;
        for (int j = tid; j < 2048; j += 256)
            if (j > b1) sa += (double)g_h1sum[n * 2048 + j];
#pragma unroll
        for (int o = 16; o; o >>= 1) sa += __shfl_down_sync(FULLM, sa, o);
        int wid = tid >> 5, lane = tid & 31;
        if (lane == 0) r_s[wid] = sa;
        __syncthreads();
        if (tid == 0) {
            double SA = 0;
#pragma unroll
            for (int w = 0; w < 8; w++) SA += r_s[w];
            float rep = __uint_as_float(((unsigned)g_b0[n] << 21) |
                                        ((unsigned)b1 << 10) | 0x200u);
            g_tk[n] = g_sumgt[n] + SA + (double)rem * (double)rep;
        }
    } else if (tid == 0) {
        g_tk[n] = 0.0;
    }

    if (tid == 0) {
        __threadfence();
        int dcount = atomicAdd(&g_seldone, 1);
        s_last = (dcount == NB - 1);
        __threadfence();
    }
    __syncthreads();
    if (s_last && tid == 0) {
        double lc = 0.0;
        long long np = 0;
        for (int b = 0; b < NB; b++) {
            lc += g_cepos[b] + g_tk[b];
            np += g_numpos[b];
        }
        double Nn = np < 1 ? 1.0 : (double)np;
        int npl = g_nposland;
        double N1 = npl < 1 ? 1.0 : (double)npl;
        out[0] = (float)(g_loss_l / Nn);
        out[1] = (float)(lc / Nn);
        out[2] = (float)(g_loss_lm / N1);
    }
}

extern "C" void kernel_launch(void* const* d_in, const int* in_sizes, int n_in,
                              void* d_out, int out_size) {
    const float4* loc     = (const float4*)d_in[0];   // (16,65536,4) f32
    const float2* conf    = (const float2*)d_in[1];   // (16,65536,2) f32
    const float2* landm   = (const float2*)d_in[2];   // (16,65536,10) f32
    const float4* priors  = (const float4*)d_in[3];   // (65536,4) f32
    const float*  targets = (const float*)d_in[4];    // (16,48,15) f32
    float* out = (float*)d_out;

    init_kernel<<<32, 256>>>();
    match_kernel<<<dim3(MBLK, NB), 256>>>(priors, targets);
    loss_kernel<<<dim3(LBLK, NB), 256>>>(loc, conf, landm, priors, targets);
    sumhist_kernel<<<dim3(CBLK, NB), 256>>>();
    final_kernel<<<NB, 256>>>(out);
}